// round 14
// baseline (speedup 1.0000x reference)
#include <cuda_runtime.h>
#include <cuda_fp16.h>
#include <cstdint>

// Problem constants
#define KDIM  512          // inner K (diagonal A folded into W)
#define NCOLS 8192         // C*S
#define APAD_ROWS 3712     // 29*128 >= 2M=3680
#define NTILES 1856        // 29 * 64
#define NCTAS  296         // 2 CTAs/SM * 148 SMs (one persistent wave)

// -------------------- scratch (static device globals) ----------------------
__device__ __half g_Ahi[APAD_ROWS * KDIM];   // PQ fp16  [3712,512]
__device__ __half g_Bhi[NCOLS * KDIM];       // x^T fp16 [8192,512]

// -------------------- small PTX helpers ------------------------------------
__device__ __forceinline__ uint32_t smem_u32(const void* p) {
    uint32_t a;
    asm("{ .reg .u64 t; cvta.to.shared.u64 t, %1; cvt.u32.u64 %0, t; }" : "=r"(a) : "l"(p));
    return a;
}
__device__ __forceinline__ void cp16(uint32_t saddr, const void* g) {
    asm volatile("cp.async.cg.shared.global [%0], [%1], 16;" :: "r"(saddr), "l"(g));
}
__device__ __forceinline__ void cp_commit() {
    asm volatile("cp.async.commit_group;" ::: "memory");
}
template<int N> __device__ __forceinline__ void cp_wait() {
    asm volatile("cp.async.wait_group %0;" :: "n"(N) : "memory");
}
__device__ __forceinline__ void ldsm4(uint32_t* r, uint32_t addr) {
    asm volatile("ldmatrix.sync.aligned.m8n8.x4.shared.b16 {%0,%1,%2,%3}, [%4];"
                 : "=r"(r[0]), "=r"(r[1]), "=r"(r[2]), "=r"(r[3]) : "r"(addr));
}
__device__ __forceinline__ void mma16816(float* c, const uint32_t* a, const uint32_t* b) {
    asm volatile(
        "mma.sync.aligned.m16n8k16.row.col.f32.f16.f16.f32 "
        "{%0,%1,%2,%3}, {%4,%5,%6,%7}, {%8,%9}, {%0,%1,%2,%3};"
        : "+f"(c[0]), "+f"(c[1]), "+f"(c[2]), "+f"(c[3])
        : "r"(a[0]), "r"(a[1]), "r"(a[2]), "r"(a[3]), "r"(b[0]), "r"(b[1]));
}

// ---------------------------------------------------------------------------
// Prep kernel (unchanged from round 13):
//   blocks [0, NB_XT):             xT tiles (64k x 32n) -> bhi fp16
//   blocks [NB_XT, NB_XT+NB_FOLD): fold -> ahi fp16, + A pad zeroing
// ---------------------------------------------------------------------------
#define NB_XT   2048
#define M_CONST 1840
#define FOLD_GRANULES (M_CONST * 128)
#define PAD_GRANULES  ((APAD_ROWS - 2 * M_CONST) * KDIM / 8)
#define NB_FOLD ((FOLD_GRANULES + PAD_GRANULES + 255) / 256)

__global__ void prep_kernel(const float* __restrict__ x,
                            const float4* __restrict__ Wr4,
                            const float4* __restrict__ Wi4,
                            const float4* __restrict__ ac4,
                            const float4* __restrict__ as4,
                            __half* __restrict__ ahi,
                            __half* __restrict__ bhi, int M)
{
    __shared__ float t[64][33];
    const int tid = threadIdx.x;

    if (blockIdx.x < NB_XT) {
        int bx = blockIdx.x;
        int k0 = (bx & 7) * 64;
        int n0 = (bx >> 3) * 32;
        int tx = tid & 31;
        int ty = tid >> 5;
        #pragma unroll
        for (int i = ty; i < 64; i += 8)
            t[i][tx] = x[(size_t)(k0 + i) * NCOLS + n0 + tx];
        __syncthreads();
        #pragma unroll
        for (int i = ty; i < 32; i += 8) {
            __half2 h = __floats2half2_rn(t[2 * tx][i], t[2 * tx + 1][i]);
            *(__half2*)(bhi + (size_t)(n0 + i) * KDIM + k0 + 2 * tx) = h;
        }
        return;
    }

    int idx = (blockIdx.x - NB_XT) * 256 + tid;
    if (idx >= FOLD_GRANULES) {
        int pidx = idx - FOLD_GRANULES;
        if (pidx < PAD_GRANULES)
            ((uint4*)(ahi + (size_t)2 * M * KDIM))[pidx] = make_uint4(0, 0, 0, 0);
        return;
    }
    int j  = idx >> 7;
    int n4 = idx & 127;
    float4 wr = Wr4[idx];
    float4 wi = Wi4[idx];
    float4 c  = ac4[n4];
    float4 s  = as4[n4];

    __half2* pa = (__half2*)(ahi + (size_t)j * KDIM + n4 * 4);
    __half2* qa = (__half2*)(ahi + (size_t)(j + M) * KDIM + n4 * 4);
    pa[0] = __floats2half2_rn(wr.x * c.x - wi.x * s.x, wr.y * c.y - wi.y * s.y);
    pa[1] = __floats2half2_rn(wr.z * c.z - wi.z * s.z, wr.w * c.w - wi.w * s.w);
    qa[0] = __floats2half2_rn(wi.x * c.x + wr.x * s.x, wi.y * c.y + wr.y * s.y);
    qa[1] = __floats2half2_rn(wi.z * c.z + wr.z * s.z, wi.w * c.w + wr.w * s.w);
}

// ---------------------------------------------------------------------------
// Persistent GEMM: 296 CTAs, each streams ~6.3 tiles (128x128, BK=32) through
// one continuous 5-stage cp.async pipeline (chunk = (tile, kt)); the ramp is
// paid once per CTA, not per tile. After its tile stream, each CTA writes its
// share of the W output (rides idle DRAM at staggered finish times).
// ---------------------------------------------------------------------------
#define OFF_AH 0
#define OFF_BH 8192
#define STAGE_BYTES 16384
#define NSTAGE 5
#define GEMM_SMEM (NSTAGE * STAGE_BYTES)   // 81920

__global__ __launch_bounds__(256, 2)
void czt_gemm_kernel(const __half* __restrict__ Ahi,
                     const __half* __restrict__ Bhi,
                     float* __restrict__ C,
                     const float4* __restrict__ Wr4,
                     const float4* __restrict__ Wi4,
                     float4* __restrict__ out4,
                     int Mrows)
{
    extern __shared__ __align__(1024) char smem[];
    const uint32_t sb = smem_u32(smem);

    const int tid  = threadIdx.x;
    const int lane = tid & 31;
    const int wid  = tid >> 5;
    const int wr   = wid >> 2;      // 0..1  (64-row slabs)
    const int wc   = wid & 3;       // 0..3  (32-col slabs)
    const int cta  = blockIdx.x;

    const int ldR   = tid >> 2;     // 0..63
    const int ldSeg = tid & 3;      // 16B segment within 64B row

    // my tiles: t = cta + i*NCTAS, i = 0..nmine-1
    const int nmine = (NTILES - 1 - cta) / NCTAS + 1;
    const int lastc = nmine * 16 - 1;

    auto issue = [&](int c) {
        const int t  = cta + (c >> 4) * NCTAS;
        const int k0 = (c & 15) * 32;
        const size_t aRowBase = (size_t)(t >> 6) * 128;
        const size_t bRowBase = (size_t)(t & 63) * 128;
        const uint32_t sbase = sb + (c % NSTAGE) * STAGE_BYTES;
        #pragma unroll
        for (int it = 0; it < 2; ++it) {
            int r = ldR + it * 64;
            uint32_t so = (uint32_t)(r * 64 + ((ldSeg ^ ((r >> 1) & 3)) << 4));
            size_t ga = (aRowBase + r) * KDIM + k0 + ldSeg * 8;
            size_t gb = (bRowBase + r) * KDIM + k0 + ldSeg * 8;
            cp16(sbase + OFF_AH + so, Ahi + ga);
            cp16(sbase + OFF_BH + so, Bhi + gb);
        }
        cp_commit();
    };

    issue(0);
    issue(1);
    issue(2);
    issue(3);

    // ldmatrix per-lane address components (CTA-tile-relative)
    const int aR   = wr * 64 + (lane & 15);                       // + mt*16
    const int aCs  = (lane >> 4);                                 // + k16*2
    const int bR   = wc * 32 + ((lane >> 4) << 3) + (lane & 7);   // + np*16
    const int bCs  = (lane >> 3) & 1;                             // + k16*2

    float acc[4][4][4] = {};

    for (int c = 0; c <= lastc; ++c) {
        const int rem = lastc - c;
        if (rem >= 3)      cp_wait<3>();
        else if (rem == 2) cp_wait<2>();
        else if (rem == 1) cp_wait<1>();
        else               cp_wait<0>();
        __syncthreads();
        if (c + 4 <= lastc) issue(c + 4);

        const uint32_t sbase = sb + (c % NSTAGE) * STAGE_BYTES;

        #pragma unroll
        for (int k16 = 0; k16 < 2; ++k16) {
            uint32_t ah[4][4], bh[8];
            #pragma unroll
            for (int mt = 0; mt < 4; ++mt) {
                int r = aR + mt * 16;
                int cs = aCs + k16 * 2;
                uint32_t so = (uint32_t)(r * 64 + ((cs ^ ((r >> 1) & 3)) << 4));
                ldsm4(ah[mt], sbase + OFF_AH + so);
            }
            #pragma unroll
            for (int np = 0; np < 2; ++np) {
                int r = bR + np * 16;
                int cs = bCs + k16 * 2;
                uint32_t so = (uint32_t)(r * 64 + ((cs ^ ((r >> 1) & 3)) << 4));
                ldsm4(&bh[np * 4], sbase + OFF_BH + so);
            }
            #pragma unroll
            for (int mt = 0; mt < 4; ++mt)
                #pragma unroll
                for (int nt = 0; nt < 4; ++nt)
                    mma16816(acc[mt][nt], ah[mt], &bh[nt * 2]);
        }

        if ((c & 15) == 15) {
            // ---- tile epilogue (registers -> gmem; no smem, no extra sync) ----
            const int t  = cta + (c >> 4) * NCTAS;
            const int by = t >> 6, bx = t & 63;
            const int rowQ = lane >> 2;
            const int colQ = (lane & 3) * 2;
            #pragma unroll
            for (int mt = 0; mt < 4; ++mt) {
                int row0 = by * 128 + wr * 64 + mt * 16 + rowQ;
                int row1 = row0 + 8;
                #pragma unroll
                for (int nt = 0; nt < 4; ++nt) {
                    int col = bx * 128 + wc * 32 + nt * 8 + colQ;
                    if (row0 < Mrows)
                        *(float2*)(C + (size_t)row0 * NCOLS + col) =
                            make_float2(acc[mt][nt][0], acc[mt][nt][1]);
                    if (row1 < Mrows)
                        *(float2*)(C + (size_t)row1 * NCOLS + col) =
                            make_float2(acc[mt][nt][2], acc[mt][nt][3]);
                }
            }
            #pragma unroll
            for (int mt = 0; mt < 4; ++mt)
                #pragma unroll
                for (int nt = 0; nt < 4; ++nt)
                    #pragma unroll
                    for (int q = 0; q < 4; ++q)
                        acc[mt][nt][q] = 0.0f;
        }
    }

    // ---- W output writer: [[Wr,-Wi],[Wi,Wr]] with hardtanh ----
    {
        const int M = Mrows >> 1;
        const int stride = NCTAS * 256;
        for (int idx = cta * 256 + tid; idx < M * 128; idx += stride) {
            int j  = idx >> 7;
            int n4 = idx & 127;
            float4 wrv = Wr4[idx];
            float4 wiv = Wi4[idx];
            wrv.x = fminf(1.f, fmaxf(-1.f, wrv.x)); wrv.y = fminf(1.f, fmaxf(-1.f, wrv.y));
            wrv.z = fminf(1.f, fmaxf(-1.f, wrv.z)); wrv.w = fminf(1.f, fmaxf(-1.f, wrv.w));
            wiv.x = fminf(1.f, fmaxf(-1.f, wiv.x)); wiv.y = fminf(1.f, fmaxf(-1.f, wiv.y));
            wiv.z = fminf(1.f, fmaxf(-1.f, wiv.z)); wiv.w = fminf(1.f, fmaxf(-1.f, wiv.w));
            float4 nwi = make_float4(-wiv.x, -wiv.y, -wiv.z, -wiv.w);
            out4[(size_t)j * 256 + n4]             = wrv;
            out4[(size_t)j * 256 + 128 + n4]       = nwi;
            out4[(size_t)(j + M) * 256 + n4]       = wiv;
            out4[(size_t)(j + M) * 256 + 128 + n4] = wrv;
        }
    }
}

// ---------------------------------------------------------------------------
// Launch.  Inputs: x, W_real, W_imag, a_cos, a_sin.
// Output: concat( W [2M,2K], X [2M, 8192] ) float32.
// ---------------------------------------------------------------------------
extern "C" void kernel_launch(void* const* d_in, const int* in_sizes, int n_in,
                              void* d_out, int out_size)
{
    const float* x   = (const float*)d_in[0];
    const float* Wr  = (const float*)d_in[1];
    const float* Wi  = (const float*)d_in[2];
    const float* ac  = (const float*)d_in[3];
    const float* as_ = (const float*)d_in[4];

    const int M = in_sizes[1] / KDIM;     // 1840
    const int Mrows = 2 * M;              // 3680

    float* out_w = (float*)d_out;                           // [2M, 2K]
    float* out_x = out_w + (size_t)Mrows * 2 * KDIM;        // [2M, 8192]

    __half *ahi, *bhi;
    cudaGetSymbolAddress((void**)&ahi, g_Ahi);
    cudaGetSymbolAddress((void**)&bhi, g_Bhi);

    // Prep: xT -> fp16  AND  PQ fold -> fp16 (+ pad zero). No W writes here.
    prep_kernel<<<NB_XT + NB_FOLD, 256>>>(
        x, (const float4*)Wr, (const float4*)Wi,
        (const float4*)ac, (const float4*)as_,
        ahi, bhi, M);

    // Persistent GEMM + W writer
    {
        cudaFuncSetAttribute(czt_gemm_kernel,
                             cudaFuncAttributeMaxDynamicSharedMemorySize, GEMM_SMEM);
        czt_gemm_kernel<<<NCTAS, 256, GEMM_SMEM>>>(
            ahi, bhi, out_x,
            (const float4*)Wr, (const float4*)Wi, (float4*)out_w,
            Mrows);
    }
}

// round 15
// speedup vs baseline: 1.2121x; 1.2121x over previous
#include <cuda_runtime.h>
#include <cuda_fp16.h>
#include <cstdint>

// Problem constants
#define KDIM  512          // inner K (diagonal A folded into W)
#define NCOLS 8192         // C*S
#define APAD_ROWS 3712     // 29*128 >= 2M=3680

// -------------------- scratch (static device globals) ----------------------
__device__ __half g_Ahi[APAD_ROWS * KDIM];   // PQ fp16  [3712,512]
__device__ __half g_Bhi[NCOLS * KDIM];       // x^T fp16 [8192,512]

// -------------------- small PTX helpers ------------------------------------
__device__ __forceinline__ uint32_t smem_u32(const void* p) {
    uint32_t a;
    asm("{ .reg .u64 t; cvta.to.shared.u64 t, %1; cvt.u32.u64 %0, t; }" : "=r"(a) : "l"(p));
    return a;
}
__device__ __forceinline__ void cp16(uint32_t saddr, const void* g) {
    asm volatile("cp.async.cg.shared.global [%0], [%1], 16;" :: "r"(saddr), "l"(g));
}
// Signal mbar when all of this thread's prior cp.asyncs have completed.
__device__ __forceinline__ void cp_arrive(uint32_t mbar) {
    asm volatile("cp.async.mbarrier.arrive.noinc.shared.b64 [%0];" :: "r"(mbar) : "memory");
}
__device__ __forceinline__ void mbar_init(uint32_t mbar, uint32_t cnt) {
    asm volatile("mbarrier.init.shared.b64 [%0], %1;" :: "r"(mbar), "r"(cnt) : "memory");
}
__device__ __forceinline__ void mbar_arrive(uint32_t mbar) {
    asm volatile("mbarrier.arrive.shared.b64 _, [%0];" :: "r"(mbar) : "memory");
}
__device__ __forceinline__ void mbar_wait(uint32_t mbar, uint32_t parity) {
    uint32_t done;
    do {
        asm volatile(
            "{\n\t.reg .pred p;\n\t"
            "mbarrier.try_wait.parity.shared.b64 p, [%1], %2;\n\t"
            "selp.b32 %0, 1, 0, p;\n\t}"
            : "=r"(done) : "r"(mbar), "r"(parity) : "memory");
    } while (!done);
}
__device__ __forceinline__ void ldsm4(uint32_t* r, uint32_t addr) {
    asm volatile("ldmatrix.sync.aligned.m8n8.x4.shared.b16 {%0,%1,%2,%3}, [%4];"
                 : "=r"(r[0]), "=r"(r[1]), "=r"(r[2]), "=r"(r[3]) : "r"(addr));
}
__device__ __forceinline__ void mma16816(float* c, const uint32_t* a, const uint32_t* b) {
    asm volatile(
        "mma.sync.aligned.m16n8k16.row.col.f32.f16.f16.f32 "
        "{%0,%1,%2,%3}, {%4,%5,%6,%7}, {%8,%9}, {%0,%1,%2,%3};"
        : "+f"(c[0]), "+f"(c[1]), "+f"(c[2]), "+f"(c[3])
        : "r"(a[0]), "r"(a[1]), "r"(a[2]), "r"(a[3]), "r"(b[0]), "r"(b[1]));
}

// ---------------------------------------------------------------------------
// Prep kernel (unchanged from round 13):
//   blocks [0, NB_XT):             xT tiles (64k x 32n) -> bhi fp16
//   blocks [NB_XT, NB_XT+NB_FOLD): fold -> ahi fp16, + A pad zeroing
// ---------------------------------------------------------------------------
#define NB_XT   2048
#define M_CONST 1840
#define FOLD_GRANULES (M_CONST * 128)
#define PAD_GRANULES  ((APAD_ROWS - 2 * M_CONST) * KDIM / 8)
#define NB_FOLD ((FOLD_GRANULES + PAD_GRANULES + 255) / 256)

__global__ void prep_kernel(const float* __restrict__ x,
                            const float4* __restrict__ Wr4,
                            const float4* __restrict__ Wi4,
                            const float4* __restrict__ ac4,
                            const float4* __restrict__ as4,
                            __half* __restrict__ ahi,
                            __half* __restrict__ bhi, int M)
{
    __shared__ float t[64][33];
    const int tid = threadIdx.x;

    if (blockIdx.x < NB_XT) {
        int bx = blockIdx.x;
        int k0 = (bx & 7) * 64;
        int n0 = (bx >> 3) * 32;
        int tx = tid & 31;
        int ty = tid >> 5;
        #pragma unroll
        for (int i = ty; i < 64; i += 8)
            t[i][tx] = x[(size_t)(k0 + i) * NCOLS + n0 + tx];
        __syncthreads();
        #pragma unroll
        for (int i = ty; i < 32; i += 8) {
            __half2 h = __floats2half2_rn(t[2 * tx][i], t[2 * tx + 1][i]);
            *(__half2*)(bhi + (size_t)(n0 + i) * KDIM + k0 + 2 * tx) = h;
        }
        return;
    }

    int idx = (blockIdx.x - NB_XT) * 256 + tid;
    if (idx >= FOLD_GRANULES) {
        int pidx = idx - FOLD_GRANULES;
        if (pidx < PAD_GRANULES)
            ((uint4*)(ahi + (size_t)2 * M * KDIM))[pidx] = make_uint4(0, 0, 0, 0);
        return;
    }
    int j  = idx >> 7;
    int n4 = idx & 127;
    float4 wr = Wr4[idx];
    float4 wi = Wi4[idx];
    float4 c  = ac4[n4];
    float4 s  = as4[n4];

    __half2* pa = (__half2*)(ahi + (size_t)j * KDIM + n4 * 4);
    __half2* qa = (__half2*)(ahi + (size_t)(j + M) * KDIM + n4 * 4);
    pa[0] = __floats2half2_rn(wr.x * c.x - wi.x * s.x, wr.y * c.y - wi.y * s.y);
    pa[1] = __floats2half2_rn(wr.z * c.z - wi.z * s.z, wr.w * c.w - wi.w * s.w);
    qa[0] = __floats2half2_rn(wi.x * c.x + wr.x * s.x, wi.y * c.y + wr.y * s.y);
    qa[1] = __floats2half2_rn(wi.z * c.z + wr.z * s.z, wi.w * c.w + wr.w * s.w);
}

// ---------------------------------------------------------------------------
// GEMM (R13 tile structure, mbarrier pipeline instead of __syncthreads):
//   blockIdx.y < 29 : 128x128 tile, BK=32, 8 warps, 5-stage cp.async ring
//                     with per-stage full/empty mbarriers (warps drift freely)
//   blockIdx.y == 29: W-output writer CTAs (ride idle DRAM in the tail)
// ---------------------------------------------------------------------------
#define OFF_AH 0
#define OFF_BH 8192
#define STAGE_BYTES 16384
#define NSTAGE 5
#define MBAR_OFF (NSTAGE * STAGE_BYTES)          // 81920
#define GEMM_SMEM (MBAR_OFF + 128)               // 82048
#define NT_ITERS (KDIM / 32)                     // 16

__global__ __launch_bounds__(256, 2)
void czt_gemm_kernel(const __half* __restrict__ Ahi,
                     const __half* __restrict__ Bhi,
                     float* __restrict__ C,
                     const float4* __restrict__ Wr4,
                     const float4* __restrict__ Wi4,
                     float4* __restrict__ out4,
                     int Mrows)
{
    const int tid = threadIdx.x;
    const int bx  = blockIdx.x;
    const int by  = blockIdx.y;

    if (by == 29) {
        // ---- W output writer: [[Wr,-Wi],[Wi,Wr]] with hardtanh ----
        const int M = Mrows >> 1;
        const int stride = 64 * 256;
        for (int idx = bx * 256 + tid; idx < M * 128; idx += stride) {
            int j  = idx >> 7;
            int n4 = idx & 127;
            float4 wrv = Wr4[idx];
            float4 wiv = Wi4[idx];
            wrv.x = fminf(1.f, fmaxf(-1.f, wrv.x)); wrv.y = fminf(1.f, fmaxf(-1.f, wrv.y));
            wrv.z = fminf(1.f, fmaxf(-1.f, wrv.z)); wrv.w = fminf(1.f, fmaxf(-1.f, wrv.w));
            wiv.x = fminf(1.f, fmaxf(-1.f, wiv.x)); wiv.y = fminf(1.f, fmaxf(-1.f, wiv.y));
            wiv.z = fminf(1.f, fmaxf(-1.f, wiv.z)); wiv.w = fminf(1.f, fmaxf(-1.f, wiv.w));
            float4 nwi = make_float4(-wiv.x, -wiv.y, -wiv.z, -wiv.w);
            out4[(size_t)j * 256 + n4]             = wrv;
            out4[(size_t)j * 256 + 128 + n4]       = nwi;
            out4[(size_t)(j + M) * 256 + n4]       = wiv;
            out4[(size_t)(j + M) * 256 + 128 + n4] = wrv;
        }
        return;
    }

    extern __shared__ __align__(1024) char smem[];
    const uint32_t sb = smem_u32(smem);

    const int lane = tid & 31;
    const int wid  = tid >> 5;
    const int wr   = wid >> 2;      // 0..1  (64-row slabs)
    const int wc   = wid & 3;       // 0..3  (32-col slabs)

    // mbarriers: full[s] at MBAR_OFF + s*8, empty[s] at MBAR_OFF + 40 + s*8
    const uint32_t mb_full  = sb + MBAR_OFF;
    const uint32_t mb_empty = sb + MBAR_OFF + NSTAGE * 8;
    if (tid == 0) {
        #pragma unroll
        for (int s = 0; s < NSTAGE; ++s) {
            mbar_init(mb_full  + s * 8, 256);  // one cp-arrive per thread
            mbar_init(mb_empty + s * 8, 8);    // one arrive per warp
        }
    }
    __syncthreads();

    const size_t aRowBase = (size_t)by * 128;   // padded, always in-bounds
    const size_t bRowBase = (size_t)bx * 128;

    const int ldR   = tid >> 2;     // 0..63
    const int ldSeg = tid & 3;      // 16B segment within 64B row

    // issue chunk k: 4 cp16s per thread + async arrive on full[k%5]
    auto issue = [&](int k) {
        const uint32_t sbase = sb + (k % NSTAGE) * STAGE_BYTES;
        const int k0 = k * 32;
        #pragma unroll
        for (int it = 0; it < 2; ++it) {
            int r = ldR + it * 64;
            uint32_t so = (uint32_t)(r * 64 + ((ldSeg ^ ((r >> 1) & 3)) << 4));
            size_t ga = (aRowBase + r) * KDIM + k0 + ldSeg * 8;
            size_t gb = (bRowBase + r) * KDIM + k0 + ldSeg * 8;
            cp16(sbase + OFF_AH + so, Ahi + ga);
            cp16(sbase + OFF_BH + so, Bhi + gb);
        }
        cp_arrive(mb_full + (k % NSTAGE) * 8);
    };

    // ramp: fills 0..3 (fill ordinal 0 for their stages -> no empty wait)
    issue(0);
    issue(1);
    issue(2);
    issue(3);

    // ldmatrix per-lane address components (CTA-tile-relative)
    const int aR   = wr * 64 + (lane & 15);                       // + mt*16
    const int aCs  = (lane >> 4);                                 // + k16*2
    const int bR   = wc * 32 + ((lane >> 4) << 3) + (lane & 7);   // + np*16
    const int bCs  = (lane >> 3) & 1;                             // + k16*2

    float acc[4][4][4] = {};

    #pragma unroll
    for (int kt = 0; kt < NT_ITERS; ++kt) {
        const uint32_t sbase = sb + (kt % NSTAGE) * STAGE_BYTES;

        // consumer: wait full[kt%5], fill ordinal kt/5 -> parity (kt/5)&1
        mbar_wait(mb_full + (kt % NSTAGE) * 8, (kt / NSTAGE) & 1);

        uint32_t ah[4][4], bh[8];
        // ---- k16 = 0 ----
        #pragma unroll
        for (int mt = 0; mt < 4; ++mt) {
            int r = aR + mt * 16;
            uint32_t so = (uint32_t)(r * 64 + (((aCs) ^ ((r >> 1) & 3)) << 4));
            ldsm4(ah[mt], sbase + OFF_AH + so);
        }
        #pragma unroll
        for (int np = 0; np < 2; ++np) {
            int r = bR + np * 16;
            uint32_t so = (uint32_t)(r * 64 + (((bCs) ^ ((r >> 1) & 3)) << 4));
            ldsm4(&bh[np * 4], sbase + OFF_BH + so);
        }
        #pragma unroll
        for (int mt = 0; mt < 4; ++mt)
            #pragma unroll
            for (int nt = 0; nt < 4; ++nt)
                mma16816(acc[mt][nt], ah[mt], &bh[nt * 2]);

        // ---- k16 = 1 loads ----
        #pragma unroll
        for (int mt = 0; mt < 4; ++mt) {
            int r = aR + mt * 16;
            uint32_t so = (uint32_t)(r * 64 + (((aCs + 2) ^ ((r >> 1) & 3)) << 4));
            ldsm4(ah[mt], sbase + OFF_AH + so);
        }
        #pragma unroll
        for (int np = 0; np < 2; ++np) {
            int r = bR + np * 16;
            uint32_t so = (uint32_t)(r * 64 + (((bCs + 2) ^ ((r >> 1) & 3)) << 4));
            ldsm4(&bh[np * 4], sbase + OFF_BH + so);
        }
        // this warp is done READING stage kt%5 (data now in regs)
        if (lane == 0) mbar_arrive(mb_empty + (kt % NSTAGE) * 8);

        // producer: issue chunk kt+4 (fill ordinal (kt+4)/5; wait empty if >0)
        if (kt + 4 < NT_ITERS) {
            const int k = kt + 4;
            if (k >= NSTAGE)
                mbar_wait(mb_empty + (k % NSTAGE) * 8, ((k / NSTAGE) - 1) & 1);
            issue(k);
        }

        // ---- k16 = 1 MMAs (cover cp.async issue latency) ----
        #pragma unroll
        for (int mt = 0; mt < 4; ++mt)
            #pragma unroll
            for (int nt = 0; nt < 4; ++nt)
                mma16816(acc[mt][nt], ah[mt], &bh[nt * 2]);
    }

    // ---- epilogue (registers -> gmem) ----
    const int rowQ = lane >> 2;
    const int colQ = (lane & 3) * 2;
    #pragma unroll
    for (int mt = 0; mt < 4; ++mt) {
        int row0 = by * 128 + wr * 64 + mt * 16 + rowQ;
        int row1 = row0 + 8;
        #pragma unroll
        for (int nt = 0; nt < 4; ++nt) {
            int col = bx * 128 + wc * 32 + nt * 8 + colQ;
            if (row0 < Mrows)
                *(float2*)(C + (size_t)row0 * NCOLS + col) =
                    make_float2(acc[mt][nt][0], acc[mt][nt][1]);
            if (row1 < Mrows)
                *(float2*)(C + (size_t)row1 * NCOLS + col) =
                    make_float2(acc[mt][nt][2], acc[mt][nt][3]);
        }
    }
}

// ---------------------------------------------------------------------------
// Launch.  Inputs: x, W_real, W_imag, a_cos, a_sin.
// Output: concat( W [2M,2K], X [2M, 8192] ) float32.
// ---------------------------------------------------------------------------
extern "C" void kernel_launch(void* const* d_in, const int* in_sizes, int n_in,
                              void* d_out, int out_size)
{
    const float* x   = (const float*)d_in[0];
    const float* Wr  = (const float*)d_in[1];
    const float* Wi  = (const float*)d_in[2];
    const float* ac  = (const float*)d_in[3];
    const float* as_ = (const float*)d_in[4];

    const int M = in_sizes[1] / KDIM;     // 1840
    const int Mrows = 2 * M;              // 3680

    float* out_w = (float*)d_out;                           // [2M, 2K]
    float* out_x = out_w + (size_t)Mrows * 2 * KDIM;        // [2M, 8192]

    __half *ahi, *bhi;
    cudaGetSymbolAddress((void**)&ahi, g_Ahi);
    cudaGetSymbolAddress((void**)&bhi, g_Bhi);

    // Prep: xT -> fp16  AND  PQ fold -> fp16 (+ pad zero). No W writes here.
    prep_kernel<<<NB_XT + NB_FOLD, 256>>>(
        x, (const float4*)Wr, (const float4*)Wi,
        (const float4*)ac, (const float4*)as_,
        ahi, bhi, M);

    // GEMM + W-writer tail row
    {
        cudaFuncSetAttribute(czt_gemm_kernel,
                             cudaFuncAttributeMaxDynamicSharedMemorySize, GEMM_SMEM);
        dim3 grid(NCOLS / 128, 30);   // y: 29 GEMM rows + 1 W-writer row
        czt_gemm_kernel<<<grid, 256, GEMM_SMEM>>>(
            ahi, bhi, out_x,
            (const float4*)Wr, (const float4*)Wi, (float4*)out_w,
            Mrows);
    }
}